// round 1
// baseline (speedup 1.0000x reference)
#include <cuda_runtime.h>
#include <math.h>
#include <stdint.h>

// Problem constants (fixed by setup_inputs)
#define HEADS  24
#define HDIM   32
#define TT     16
#define S_SP   1560            // th*tw = 30*52
#define BATCH  2
#define CDIM   768
#define INMLP  792             // C + PAD_T*mouse_dim = 768 + 24
#define NROWS  (BATCH*S_SP*TT) // 49920
#define NF     61              // (tt-1)*R+1
#define PADT   12

// Scratch (static device globals; no runtime allocation)
__device__ float g_z   [(size_t)NROWS * INMLP];
__device__ float g_h   [(size_t)NROWS * INMLP];
__device__ float g_feat[(size_t)NROWS * CDIM];
__device__ float g_qkv [(size_t)NROWS * 3 * CDIM];
__device__ float g_attn[(size_t)NROWS * CDIM];

// ---------------------------------------------------------------------------
// Kernel 1: build z = concat(hs, gathered mouse)   (49920 x 792)
// row r = (b*S + s)*TT + t ;  hs part = x[b, t*S + s, :]
// ---------------------------------------------------------------------------
__global__ void build_z_kernel(const float* __restrict__ x,
                               const float* __restrict__ mouse)
{
    int r = blockIdx.x;
    int bs = r / TT, t = r % TT;
    int b_idx = bs / S_SP, s = bs % S_SP;

    const float4* xr = reinterpret_cast<const float4*>(
        x + ((size_t)b_idx * (TT * S_SP) + (size_t)t * S_SP + s) * CDIM);
    float* zr = g_z + (size_t)r * INMLP;
    float4* zr4 = reinterpret_cast<float4*>(zr);

    for (int c = threadIdx.x; c < CDIM / 4; c += blockDim.x)
        zr4[c] = xr[c];

    if (threadIdx.x < 24) {
        int j  = threadIdx.x >> 1;   // 0..11
        int ch = threadIdx.x & 1;    // 0..1
        int i  = 4 * t + j;          // padded index (R=4)
        float v = 0.0f;
        if (i >= PADT) v = mouse[((size_t)b_idx * NF + (i - PADT)) * 2 + ch];
        zr[CDIM + threadIdx.x] = v;
    }
}

// ---------------------------------------------------------------------------
// SGEMM: C = A(MxK) * B(KxN) + epilogue
// EPI: 0 none, 1 +bias, 2 +bias then gelu(tanh), 3 +residual(res)
// A is selected from device globals via a_sel; C via c_sel (4 = external ptr)
// BM=BN=128, BK=8, 256 threads, 8x8 per thread. M % 128 == 0, K % 8 == 0,
// K % 4 == 0, N % 4 == 0 guaranteed by problem shapes; N edge guarded.
// ---------------------------------------------------------------------------
template<int EPI>
__global__ __launch_bounds__(256)
void sgemm_kernel(int a_sel, const float* __restrict__ B,
                  const float* __restrict__ bias,
                  const float* __restrict__ res,
                  float* __restrict__ Cext, int c_sel,
                  int M, int N, int K)
{
    const float* A = (a_sel == 0) ? g_z :
                     (a_sel == 1) ? g_h :
                     (a_sel == 2) ? g_feat : g_attn;
    float* C = (c_sel == 0) ? g_h :
               (c_sel == 1) ? g_feat :
               (c_sel == 2) ? g_qkv :
               (c_sel == 3) ? g_attn : Cext;

    const int BM = 128, BN = 128, BK = 8, TM = 8, TN = 8;
    __shared__ float As[BK][BM];
    __shared__ float Bs[BK][BN];

    int tid  = threadIdx.x;
    int bcol = blockIdx.x * BN;
    int brow = blockIdx.y * BM;
    int trow = (tid / 16) * TM;
    int tcol = (tid % 16) * TN;

    int a_row = tid >> 1;
    int a_col = (tid & 1) * 4;
    int b_row = tid >> 5;
    int b_col = (tid & 31) * 4;

    float acc[TM][TN] = {};

    const float* Aptr = A + (size_t)(brow + a_row) * K + a_col;
    const float* Bptr = B + (size_t)b_row * N + bcol + b_col;
    bool bvalid = (bcol + b_col) < N;   // N % 4 == 0 -> all-or-nothing float4

    for (int k0 = 0; k0 < K; k0 += BK) {
        float4 av = *reinterpret_cast<const float4*>(Aptr + k0);
        As[a_col + 0][a_row] = av.x;
        As[a_col + 1][a_row] = av.y;
        As[a_col + 2][a_row] = av.z;
        As[a_col + 3][a_row] = av.w;

        float4 bv = make_float4(0.f, 0.f, 0.f, 0.f);
        if (bvalid) bv = *reinterpret_cast<const float4*>(Bptr + (size_t)k0 * N);
        *reinterpret_cast<float4*>(&Bs[b_row][b_col]) = bv;

        __syncthreads();

        #pragma unroll
        for (int kk = 0; kk < BK; kk++) {
            float4 a0 = *reinterpret_cast<const float4*>(&As[kk][trow]);
            float4 a1 = *reinterpret_cast<const float4*>(&As[kk][trow + 4]);
            float4 b0 = *reinterpret_cast<const float4*>(&Bs[kk][tcol]);
            float4 b1 = *reinterpret_cast<const float4*>(&Bs[kk][tcol + 4]);
            float af[TM] = {a0.x, a0.y, a0.z, a0.w, a1.x, a1.y, a1.z, a1.w};
            float bf[TN] = {b0.x, b0.y, b0.z, b0.w, b1.x, b1.y, b1.z, b1.w};
            #pragma unroll
            for (int i = 0; i < TM; i++)
                #pragma unroll
                for (int j = 0; j < TN; j++)
                    acc[i][j] = fmaf(af[i], bf[j], acc[i][j]);
        }
        __syncthreads();
    }

    #pragma unroll
    for (int i = 0; i < TM; i++) {
        int row = brow + trow + i;
        #pragma unroll
        for (int j = 0; j < TN; j++) {
            int col = bcol + tcol + j;
            if (col >= N) continue;
            float v = acc[i][j];
            if (EPI == 1) v += bias[col];
            if (EPI == 2) {
                v += bias[col];
                float u = 0.7978845608028654f * (v + 0.044715f * v * v * v);
                v = 0.5f * v * (1.0f + tanhf(u));
            }
            if (EPI == 3) v += res[(size_t)row * N + col];
            C[(size_t)row * N + col] = v;
        }
    }
}

// ---------------------------------------------------------------------------
// Attention: one warp per (bs, head). q,k,v are (TT=16, 32).
// RMSNorm(q,k) -> RoPE (first 24 dims temporal, last 8 identity) ->
// softmax(q k^T / sqrt(32)) v. Output written in (b, t*S+s) row order.
// ---------------------------------------------------------------------------
__global__ __launch_bounds__(128)
void attn_kernel(const float* __restrict__ q_gamma,
                 const float* __restrict__ k_gamma)
{
    __shared__ float qs[4][TT][33];
    __shared__ float ks[4][TT][33];
    __shared__ float vs[4][TT][32];
    __shared__ float ps[4][TT][17];

    int warp = threadIdx.x >> 5;
    int lane = threadIdx.x & 31;
    int gw = blockIdx.x * 4 + warp;           // 0 .. 74879
    int head = gw % HEADS;
    int bs   = gw / HEADS;
    int b_idx = bs / S_SP;
    int s     = bs % S_SP;

    float q[TT], k[TT], v[TT];
    #pragma unroll
    for (int t = 0; t < TT; t++) {
        size_t base = ((size_t)(bs * TT + t)) * (3 * CDIM) + head * HDIM + lane;
        q[t] = g_qkv[base];
        k[t] = g_qkv[base + CDIM];
        v[t] = g_qkv[base + 2 * CDIM];
    }

    float qg = q_gamma[lane], kg = k_gamma[lane];
    float freq = 0.0f;
    if (lane < 24) {
        int p = lane >> 1;                    // pair index 0..11
        freq = exp2f(-8.0f * (float)(2 * p) / 24.0f);  // 256^(-2p/24)
    }

    #pragma unroll
    for (int t = 0; t < TT; t++) {
        float sq = q[t] * q[t];
        float sk = k[t] * k[t];
        #pragma unroll
        for (int o = 16; o > 0; o >>= 1) {
            sq += __shfl_xor_sync(0xffffffffu, sq, o);
            sk += __shfl_xor_sync(0xffffffffu, sk, o);
        }
        float qn = q[t] * rsqrtf(sq * (1.0f / 32.0f) + 1e-6f) * qg;
        float kn = k[t] * rsqrtf(sk * (1.0f / 32.0f) + 1e-6f) * kg;

        float c = 1.0f, sn = 0.0f;
        if (lane < 24) {
            float ang = freq * (float)t;
            c = cosf(ang);
            sn = sinf(ang);
        }
        float qr = __shfl_xor_sync(0xffffffffu, qn, 1);
        float kr = __shfl_xor_sync(0xffffffffu, kn, 1);
        qr = (lane & 1) ? qr : -qr;           // rotate_half
        kr = (lane & 1) ? kr : -kr;

        qs[warp][t][lane] = qn * c + qr * sn;
        ks[warp][t][lane] = kn * c + kr * sn;
        vs[warp][t][lane] = v[t];
    }
    __syncwarp();

    const float scale = 0.17677669529663687f;  // 32^-0.5
    #pragma unroll
    for (int i = 0; i < 8; i++) {
        int idx = lane * 8 + i;
        int t = idx >> 4, m = idx & 15;
        float sum = 0.0f;
        #pragma unroll
        for (int d = 0; d < HDIM; d++)
            sum = fmaf(qs[warp][t][d], ks[warp][m][d], sum);
        ps[warp][t][m] = sum * scale;
    }
    __syncwarp();

    if (lane < 16) {
        float mx = -1e30f;
        #pragma unroll
        for (int m = 0; m < 16; m++) mx = fmaxf(mx, ps[warp][lane][m]);
        float sum = 0.0f;
        #pragma unroll
        for (int m = 0; m < 16; m++) {
            float e = expf(ps[warp][lane][m] - mx);
            ps[warp][lane][m] = e;
            sum += e;
        }
        float inv = 1.0f / sum;
        #pragma unroll
        for (int m = 0; m < 16; m++) ps[warp][lane][m] *= inv;
    }
    __syncwarp();

    #pragma unroll
    for (int t = 0; t < TT; t++) {
        float o = 0.0f;
        #pragma unroll
        for (int m = 0; m < 16; m++)
            o = fmaf(ps[warp][t][m], vs[warp][m][lane], o);
        size_t orow = (size_t)b_idx * (TT * S_SP) + (size_t)t * S_SP + s;
        g_attn[orow * CDIM + head * HDIM + lane] = o;
    }
}

// ---------------------------------------------------------------------------
extern "C" void kernel_launch(void* const* d_in, const int* in_sizes, int n_in,
                              void* d_out, int out_size)
{
    const float* mouse = (const float*)d_in[0];
    // d_in[1] = keyboard_condition (unused by reference)
    const float* x     = (const float*)d_in[2];
    const float* w1    = (const float*)d_in[3];
    const float* b1    = (const float*)d_in[4];
    const float* w2    = (const float*)d_in[5];
    const float* b2    = (const float*)d_in[6];
    const float* qkvw  = (const float*)d_in[7];
    const float* qg    = (const float*)d_in[8];
    const float* kg    = (const float*)d_in[9];
    const float* pw    = (const float*)d_in[10];
    float* out = (float*)d_out;

    // 1) gather z
    build_z_kernel<<<NROWS, 128>>>(x, mouse);

    // 2) h = gelu(z @ w1 + b1)              (49920 x 792) @ (792 x 792)
    {
        dim3 grid((INMLP + 127) / 128, NROWS / 128);
        sgemm_kernel<2><<<grid, 256>>>(0, w1, b1, nullptr, nullptr, 0,
                                       NROWS, INMLP, INMLP);
    }
    // 3) feat = h @ w2 + b2                 (49920 x 792) @ (792 x 768)
    {
        dim3 grid(CDIM / 128, NROWS / 128);
        sgemm_kernel<1><<<grid, 256>>>(1, w2, b2, nullptr, nullptr, 1,
                                       NROWS, CDIM, INMLP);
    }
    // 4) qkv = feat @ qkv_w                 (49920 x 768) @ (768 x 2304)
    {
        dim3 grid((3 * CDIM) / 128, NROWS / 128);
        sgemm_kernel<0><<<grid, 256>>>(2, qkvw, nullptr, nullptr, nullptr, 2,
                                       NROWS, 3 * CDIM, CDIM);
    }
    // 5) attention -> g_attn (already permuted back to x row order)
    attn_kernel<<<(BATCH * S_SP * HEADS) / 4, 128>>>(qg, kg);

    // 6) out = x + g_attn @ proj_w          (49920 x 768) @ (768 x 768)
    {
        dim3 grid(CDIM / 128, NROWS / 128);
        sgemm_kernel<3><<<grid, 256>>>(3, pw, nullptr, x, out, 4,
                                       NROWS, CDIM, CDIM);
    }
    (void)in_sizes; (void)n_in; (void)out_size;
}